// round 17
// baseline (speedup 1.0000x reference)
#include <cuda_runtime.h>
#include <cuda_bf16.h>

#define BB 512
#define TT 512
#define LL 128
#define PADL 0
#define BOSL 1
#define EOSL 2

__device__ float g_res[BB];
__device__ int   g_perm[BB];    // batch ids sorted by length (ascending)
__device__ int   g_len[BB];     // length per batch id
__device__ int   g_ticket;      // zero-initialized; reset by last CTA each run

// ---- prep 1: parallel length count (one CTA per batch) ----
__global__ void crf_count(const int* __restrict__ mask) {
    const int b    = blockIdx.x;
    const int t    = threadIdx.x;
    const int lane = t & 31;
    const int wid  = t >> 5;
    __shared__ int sred[4];

    int cnt = 0;
#pragma unroll
    for (int q = t; q < TT; q += 128) cnt += (mask[b * TT + q] != 0) ? 1 : 0;
#pragma unroll
    for (int o = 16; o > 0; o >>= 1) cnt += __shfl_down_sync(0xffffffffu, cnt, o);
    if (lane == 0) sred[wid] = cnt;
    __syncthreads();
    if (t == 0) g_len[b] = sred[0] + sred[1] + sred[2] + sred[3];
}

// ---- prep 2: bitonic sort of 512 (len, id) pairs (1 CTA) ----
__global__ void crf_sort() {
    __shared__ int sk[BB];
    __shared__ int sv[BB];
    const int t = threadIdx.x;
    sk[t] = g_len[t];
    sv[t] = t;
    __syncthreads();
    for (int k = 2; k <= BB; k <<= 1) {
        for (int jj = k >> 1; jj > 0; jj >>= 1) {
            int ixj = t ^ jj;
            if (ixj > t) {
                bool dir = ((t & k) == 0);
                if ((sk[t] > sk[ixj]) == dir) {
                    int tk = sk[t]; sk[t] = sk[ixj]; sk[ixj] = tk;
                    int tv = sv[t]; sv[t] = sv[ixj]; sv[ixj] = tv;
                }
            }
            __syncthreads();
        }
    }
    g_perm[t] = sv[t];
}

// ---- forward: CTA x handles (rank x, rank 511-x); bf16 HFMA2 inner loop.
//      Last CTA to finish also does the final mean (fused reduce).
__global__ __launch_bounds__(128, 2) void crf_fwd(
    const float* __restrict__ feat,   // [B, T, L] f32
    const int* __restrict__ tags,     // [B, T] i32
    const float* __restrict__ tr,     // [L, L] f32
    float* __restrict__ out)          // scalar NLL
{
    const int j    = threadIdx.x;   // label column 0..127
    const int x    = blockIdx.x;
    const int lane = j & 31;
    const int wid  = j >> 5;

    __shared__ __align__(16) __nv_bfloat16 u_sh[2][2][LL];  // [buf][slot][i]
    __shared__ float c_sh[2][2];
    __shared__ float s_red[2][4];
    __shared__ float s_gold[2];
    __shared__ int   s_bid[2];
    __shared__ int   s_last;

    if (j == 0) s_bid[0] = g_perm[x];
    if (j == 1) s_bid[1] = g_perm[BB - 1 - x];
    __syncthreads();
    const int bA = s_bid[0];
    const int bB = s_bid[1];
    const int lenA = g_len[bA];
    const int lenB = g_len[bB];

    // ---- E column j as bf16x2: E2h[m] = (E[2m][j], E[2m+1][j])
    __nv_bfloat162 E2h[64];
#pragma unroll
    for (int m = 0; m < 64; m++) {
        float lo = __expf(tr[(2 * m)     * LL + j]);
        float hi = __expf(tr[(2 * m + 1) * LL + j]);
        E2h[m] = __floats2bfloat162_rn(lo, hi);
    }

    // ---- gold path scores (fp32, exact)
    for (int sb = 0; sb < 2; sb++) {
        const int bb = (sb == 0) ? bA : bB;
        const int lb = (sb == 0) ? lenA : lenB;
        float gp = 0.0f;
        for (int t = j; t < lb; t += 128) {
            int tg   = tags[bb * TT + t];
            float e  = feat[(bb * TT + t) * LL + tg];
            int prev = (t == 0) ? BOSL : tags[bb * TT + t - 1];
            gp += e + tr[prev * LL + tg];
        }
#pragma unroll
        for (int o = 16; o > 0; o >>= 1) gp += __shfl_down_sync(0xffffffffu, gp, o);
        if (lane == 0) s_red[sb][wid] = gp;
    }
    __syncthreads();
    if (j < 2) {
        const int sb = j;
        const int bb = (sb == 0) ? bA : bB;
        const int lb = (sb == 0) ? lenA : lenB;
        float g = s_red[sb][0] + s_red[sb][1] + s_red[sb][2] + s_red[sb][3];
        g += tr[tags[bb * TT + lb - 1] * LL + EOSL];
        s_gold[sb] = g;
    }

    // ---- init: fv = tr[BOS,:] + feat[:,0,:]
    const float trb = tr[BOSL * LL + j];
    float fvA = trb + feat[(bA * TT) * LL + j];
    float fvB = trb + feat[(bB * TT) * LL + j];
    if (j == 64) { c_sh[0][0] = fvA; c_sh[0][1] = fvB; }
    __syncthreads();
    float cA = c_sh[0][0];
    float cB = c_sh[0][1];

    float ftA = __ldcs(&feat[(bA * TT + 1) * LL + j]);  // len >= 256 always
    float ftB = __ldcs(&feat[(bB * TT + 1) * LL + j]);

    const __nv_bfloat162 z2 = __floats2bfloat162_rn(0.0f, 0.0f);
    int p = 0;

    // ======== Phase 1: both batches active (t = 1 .. lenA-1) ========
    for (int t = 1; t < lenA; t++) {
        float uA = __expf(fvA - cA);
        float uB = __expf(fvB - cB);
        u_sh[p][0][j] = __float2bfloat16_rn(uA);
        u_sh[p][1][j] = __float2bfloat16_rn(uB);
        if (j == 64) { c_sh[p][0] = fvA; c_sh[p][1] = fvB; }

        // issue next-step emission loads BEFORE the barrier (independent of u)
        float nftA = (t + 1 < lenA) ? __ldcs(&feat[(bA * TT + t + 1) * LL + j]) : 0.0f;
        float nftB = (t + 1 < lenB) ? __ldcs(&feat[(bB * TT + t + 1) * LL + j]) : 0.0f;

        __syncthreads();
        float ncA = c_sh[p][0];
        float ncB = c_sh[p][1];

        const float4* U0 = (const float4*)(&u_sh[p][0][0]);
        const float4* U1 = (const float4*)(&u_sh[p][1][0]);
        __nv_bfloat162 accA[8], accB[8];
#pragma unroll
        for (int r = 0; r < 8; r++) { accA[r] = z2; accB[r] = z2; }
#pragma unroll
        for (int q = 0; q < 16; q++) {
            float4 va = U0[q];
            float4 vb = U1[q];
            const __nv_bfloat162* wa = (const __nv_bfloat162*)&va;
            const __nv_bfloat162* wb = (const __nv_bfloat162*)&vb;
#pragma unroll
            for (int r = 0; r < 4; r++) {
                int m = 4 * q + r;
                accA[m & 7] = __hfma2(wa[r], E2h[m], accA[m & 7]);
                accB[m & 7] = __hfma2(wb[r], E2h[m], accB[m & 7]);
            }
        }
#pragma unroll
        for (int r = 0; r < 4; r++) { accA[r] = __hadd2(accA[r], accA[r + 4]);
                                      accB[r] = __hadd2(accB[r], accB[r + 4]); }
        accA[0] = __hadd2(accA[0], accA[2]); accA[1] = __hadd2(accA[1], accA[3]);
        accB[0] = __hadd2(accB[0], accB[2]); accB[1] = __hadd2(accB[1], accB[3]);
        accA[0] = __hadd2(accA[0], accA[1]);
        accB[0] = __hadd2(accB[0], accB[1]);
        float sA = __bfloat162float(__low2bfloat16(accA[0]))
                 + __bfloat162float(__high2bfloat16(accA[0]));
        float sB = __bfloat162float(__low2bfloat16(accB[0]))
                 + __bfloat162float(__high2bfloat16(accB[0]));

        fvA = ftA + cA + __logf(sA);
        fvB = ftB + cB + __logf(sB);
        cA = ncA; cB = ncB;
        ftA = nftA; ftB = nftB;
        p ^= 1;
    }

    // ======== Phase 2: only batch B (t = lenA .. lenB-1) ========
    for (int t = lenA; t < lenB; t++) {
        float uB = __expf(fvB - cB);
        u_sh[p][1][j] = __float2bfloat16_rn(uB);
        if (j == 64) c_sh[p][1] = fvB;

        float nftB = (t + 1 < lenB) ? __ldcs(&feat[(bB * TT + t + 1) * LL + j]) : 0.0f;

        __syncthreads();
        float ncB = c_sh[p][1];

        const float4* U1 = (const float4*)(&u_sh[p][1][0]);
        __nv_bfloat162 accB[8];
#pragma unroll
        for (int r = 0; r < 8; r++) accB[r] = z2;
#pragma unroll
        for (int q = 0; q < 16; q++) {
            float4 vb = U1[q];
            const __nv_bfloat162* wb = (const __nv_bfloat162*)&vb;
#pragma unroll
            for (int r = 0; r < 4; r++) {
                int m = 4 * q + r;
                accB[m & 7] = __hfma2(wb[r], E2h[m], accB[m & 7]);
            }
        }
#pragma unroll
        for (int r = 0; r < 4; r++) accB[r] = __hadd2(accB[r], accB[r + 4]);
        accB[0] = __hadd2(accB[0], accB[2]); accB[1] = __hadd2(accB[1], accB[3]);
        accB[0] = __hadd2(accB[0], accB[1]);
        float sB = __bfloat162float(__low2bfloat16(accB[0]))
                 + __bfloat162float(__high2bfloat16(accB[0]));

        fvB = ftB + cB + __logf(sB);
        cB = ncB;
        ftB = nftB;
        p ^= 1;
    }

    // ---- logZ = logsumexp_j(fv[j] + tr[j][EOS]); per-batch results
    {
        float te = tr[j * LL + EOSL];
        float eA = __expf((fvA + te) - cA);
        float eB = __expf((fvB + te) - cB);
#pragma unroll
        for (int o = 16; o > 0; o >>= 1) {
            eA += __shfl_down_sync(0xffffffffu, eA, o);
            eB += __shfl_down_sync(0xffffffffu, eB, o);
        }
        __syncthreads();
        if (lane == 0) { s_red[0][wid] = eA; s_red[1][wid] = eB; }
        __syncthreads();
        if (j == 0) {
            float zA = s_red[0][0] + s_red[0][1] + s_red[0][2] + s_red[0][3];
            float zB = s_red[1][0] + s_red[1][1] + s_red[1][2] + s_red[1][3];
            g_res[bA] = (cA + __logf(zA)) - s_gold[0];
            g_res[bB] = (cB + __logf(zB)) - s_gold[1];
        }
    }

    // ---- fused reduce: last CTA computes the deterministic fixed-order mean
    __threadfence();
    __syncthreads();
    if (j == 0) s_last = (atomicAdd(&g_ticket, 1) == (int)gridDim.x - 1) ? 1 : 0;
    __syncthreads();
    if (s_last) {
        __threadfence();
        // 128 threads; thread j sums g_res[j], g_res[j+128], ... in fixed order
        float v = g_res[j] + g_res[j + 128] + g_res[j + 256] + g_res[j + 384];
#pragma unroll
        for (int o = 16; o > 0; o >>= 1) v += __shfl_down_sync(0xffffffffu, v, o);
        if (lane == 0) s_red[0][wid] = v;
        __syncthreads();
        if (j == 0) {
            out[0] = (s_red[0][0] + s_red[0][1] + s_red[0][2] + s_red[0][3])
                     * (1.0f / (float)BB);
            g_ticket = 0;   // reset for next graph replay
        }
    }
}

extern "C" void kernel_launch(void* const* d_in, const int* in_sizes, int n_in,
                              void* d_out, int out_size) {
    const float* feat = (const float*)d_in[0];
    const int*   tags = (const int*)d_in[1];
    const int*   mask = (const int*)d_in[2];
    const float* tr   = (const float*)d_in[3];

    crf_count<<<BB, 128>>>(mask);
    crf_sort<<<1, BB>>>();
    crf_fwd<<<BB / 2, 128>>>(feat, tags, tr, (float*)d_out);
}